// round 1
// baseline (speedup 1.0000x reference)
#include <cuda_runtime.h>
#include <cstdint>

#define B_   8
#define N_   1024
#define C_   768
#define H_   12
#define D_   64
#define BH_  96
#define M_   8192
#define O3_  2304

// Scratch (static __device__ — no allocation in kernel_launch)
__device__ int8_t g_spk[3][BH_][N_][D_];            // q/k/v ternary spikes, ~18.9MB
__device__ int8_t g_dots[(size_t)BH_ * N_ * N_];    // exact integer logits, ~100.7MB
__device__ int8_t g_s[M_][C_];                      // post-attention spikes
__device__ int    g_flag[M_];                       // per-row "any head spiked" flag

__device__ __forceinline__ int spike_of(float v) {
    float u = v + 0.5f;                 // replicate reference fp32 op order
    return (u >= 1.0f) ? 1 : ((u < 0.0f) ? -1 : 0);
}

// ---------------------------------------------------------------------------
// Kernel A: QKV projection (fp32 exact), emits ternary spikes to g_spk.
// out[m,o] = sum_c x[m,c] * w_qkv[o,c];  M=8192, N=2304, K=768
// ---------------------------------------------------------------------------
__global__ void __launch_bounds__(256) qkv_kernel(const float* __restrict__ x,
                                                  const float* __restrict__ w) {
    __shared__ float As[16][64];   // [k][m] transposed
    __shared__ float Bs[16][64];   // [k][o] transposed
    const int t  = threadIdx.x;
    const int tx = t & 15, ty = t >> 4;
    const int m0 = blockIdx.y * 64, o0 = blockIdx.x * 64;
    const int lr = t >> 2, lc = (t & 3) * 4;

    float acc[4][4] = {};
    for (int k0 = 0; k0 < 768; k0 += 16) {
        float4 av = *(const float4*)&x[(size_t)(m0 + lr) * 768 + k0 + lc];
        float4 bv = *(const float4*)&w[(size_t)(o0 + lr) * 768 + k0 + lc];
        __syncthreads();
        As[lc + 0][lr] = av.x; As[lc + 1][lr] = av.y;
        As[lc + 2][lr] = av.z; As[lc + 3][lr] = av.w;
        Bs[lc + 0][lr] = bv.x; Bs[lc + 1][lr] = bv.y;
        Bs[lc + 2][lr] = bv.z; Bs[lc + 3][lr] = bv.w;
        __syncthreads();
#pragma unroll
        for (int k = 0; k < 16; k++) {
            float4 a = *(const float4*)&As[k][ty * 4];
            float4 b = *(const float4*)&Bs[k][tx * 4];
            float ar[4] = {a.x, a.y, a.z, a.w};
            float br[4] = {b.x, b.y, b.z, b.w};
#pragma unroll
            for (int i = 0; i < 4; i++)
#pragma unroll
                for (int j = 0; j < 4; j++)
                    acc[i][j] = fmaf(ar[i], br[j], acc[i][j]);
        }
    }
#pragma unroll
    for (int i = 0; i < 4; i++) {
        int m = m0 + ty * 4 + i;
        int b = m >> 10, n = m & 1023;
#pragma unroll
        for (int j = 0; j < 4; j++) {
            int o   = o0 + tx * 4 + j;
            int tt  = o / 768;          // 0=q, 1=k, 2=v
            int rem = o - tt * 768;
            int h   = rem >> 6, d = rem & 63;
            g_spk[tt][b * H_ + h][n][d] = (int8_t)spike_of(acc[i][j]);
        }
    }
}

// ---------------------------------------------------------------------------
// Kernel B1: exact integer attention logits via s8 IMMA.
// dots[bh][n][m] = sum_d sq[n,d]*sk[m,d]  (range [-64,64], fits int8)
// Block: 128 thr (4 warps), covers 64 rows x all 1024 cols. mma.m16n8k32.
// ---------------------------------------------------------------------------
__global__ void __launch_bounds__(128) logits_kernel() {
    __shared__ int8_t ssq[64][64];
    __shared__ int8_t ssk[64][64];
    const int t    = threadIdx.x;
    const int lane = t & 31, wrp = t >> 5;
    const int gid  = lane >> 2, tig = lane & 3;
    const int bh   = blockIdx.y, n0 = blockIdx.x * 64;

    {   // cooperative load of sq rows (contiguous 4KB)
        const int4* src = (const int4*)&g_spk[0][bh][n0][0];
        int4* dst = (int4*)&ssq[0][0];
        dst[t] = src[t]; dst[t + 128] = src[t + 128];
    }
    __syncthreads();

    // A fragments (fixed for this block): 2 k-steps of 32
    int afr[2][4];
#pragma unroll
    for (int ks = 0; ks < 2; ks++) {
        int r = wrp * 16 + gid;
        afr[ks][0] = *(const int*)&ssq[r    ][ks * 32 + tig * 4];
        afr[ks][1] = *(const int*)&ssq[r + 8][ks * 32 + tig * 4];
        afr[ks][2] = *(const int*)&ssq[r    ][ks * 32 + 16 + tig * 4];
        afr[ks][3] = *(const int*)&ssq[r + 8][ks * 32 + 16 + tig * 4];
    }

    const size_t base = (size_t)bh * N_ * N_;
    for (int mc = 0; mc < 16; mc++) {
        __syncthreads();
        {   // load sk chunk (64 rows)
            const int4* src = (const int4*)&g_spk[1][bh][mc * 64][0];
            int4* dst = (int4*)&ssk[0][0];
            dst[t] = src[t]; dst[t + 128] = src[t + 128];
        }
        __syncthreads();
#pragma unroll
        for (int c = 0; c < 8; c++) {
            int c0 = 0, c1 = 0, c2 = 0, c3 = 0;
#pragma unroll
            for (int ks = 0; ks < 2; ks++) {
                int b0 = *(const int*)&ssk[c * 8 + gid][ks * 32 + tig * 4];
                int b1 = *(const int*)&ssk[c * 8 + gid][ks * 32 + 16 + tig * 4];
                asm volatile(
                    "mma.sync.aligned.m16n8k32.row.col.s32.s8.s8.s32 "
                    "{%0,%1,%2,%3}, {%4,%5,%6,%7}, {%8,%9}, {%0,%1,%2,%3};"
                    : "+r"(c0), "+r"(c1), "+r"(c2), "+r"(c3)
                    : "r"(afr[ks][0]), "r"(afr[ks][1]), "r"(afr[ks][2]), "r"(afr[ks][3]),
                      "r"(b0), "r"(b1));
            }
            int row = n0 + wrp * 16 + gid;
            int col = mc * 64 + c * 8 + tig * 2;
            char2 lo; lo.x = (char)c0; lo.y = (char)c1;
            char2 hi; hi.x = (char)c2; hi.y = (char)c3;
            *(char2*)&g_dots[base + (size_t)row * N_ + col]       = lo;
            *(char2*)&g_dots[base + (size_t)(row + 8) * N_ + col] = hi;
        }
    }
}

// ---------------------------------------------------------------------------
// Kernel Z: zero the row flags (graph replays need deterministic reset).
// ---------------------------------------------------------------------------
__global__ void zero_flags() {
    int i = blockIdx.x * blockDim.x + threadIdx.x;
    if (i < M_) g_flag[i] = 0;
}

// ---------------------------------------------------------------------------
// Kernel B2: per (bh,row): max, sumexp, argmax; spike iff 1/S + 0.5 >= 1.
// Winner row's v-spikes copied to g_s; else zeros. One warp per row.
// ---------------------------------------------------------------------------
__global__ void __launch_bounds__(256) softmax_select_kernel() {
    const int t = threadIdx.x, lane = t & 31, wrp = t >> 5;
    const int bh = blockIdx.y;
    const int n  = blockIdx.x * 8 + wrp;
    const int b  = bh / H_, h = bh - b * H_;

    const int8_t* row = &g_dots[(size_t)bh * N_ * N_ + (size_t)n * N_];
    int4 v0 = ((const int4*)row)[lane];
    int4 v1 = ((const int4*)row)[lane + 32];
    int words[8] = {v0.x, v0.y, v0.z, v0.w, v1.x, v1.y, v1.z, v1.w};

    int lmax = -1000;
#pragma unroll
    for (int wi = 0; wi < 8; wi++)
#pragma unroll
        for (int j = 0; j < 4; j++) {
            int val = (words[wi] << (24 - 8 * j)) >> 24;
            lmax = max(lmax, val);
        }
#pragma unroll
    for (int off = 16; off; off >>= 1)
        lmax = max(lmax, __shfl_xor_sync(0xffffffffu, lmax, off));

    float s = 0.0f;
    int larg = 0x7fffffff;
#pragma unroll
    for (int wi = 0; wi < 8; wi++) {
        int colbase = (wi < 4) ? (lane * 16 + wi * 4) : (512 + lane * 16 + (wi - 4) * 4);
#pragma unroll
        for (int j = 0; j < 4; j++) {
            int val = (words[wi] << (24 - 8 * j)) >> 24;
            s += expf(0.125f * (float)(val - lmax));   // scale = D^-0.5 = 0.125 exact
            if (val == lmax) larg = min(larg, colbase + j);
        }
    }
#pragma unroll
    for (int off = 16; off; off >>= 1) {
        s    += __shfl_xor_sync(0xffffffffu, s, off);
        larg  = min(larg, __shfl_xor_sync(0xffffffffu, larg, off));
    }

    float p   = 1.0f / s;                 // softmax at argmax (exp(0)=1 numerator)
    bool  spk = (p + 0.5f) >= 1.0f;       // attn-IF: binary spike; only argmax can pass

    int* dst = (int*)&g_s[b * N_ + n][h * D_];
    if (spk) {
        const int* src = (const int*)&g_spk[2][bh][larg][0];
        if (lane < 16) dst[lane] = src[lane];   // out = v-spikes; sign() is identity
        if (lane == 0) g_flag[b * N_ + n] = 1;  // benign racing writes of 1
    } else {
        if (lane < 16) dst[lane] = 0;
    }
}

// ---------------------------------------------------------------------------
// Kernel C: output projection (fp32 exact) + final IF, with zero-tile skip.
// out[m,o] = spike( sum_c s[m,c] * w_proj[o,c] )
// ---------------------------------------------------------------------------
__global__ void __launch_bounds__(256) proj_kernel(const float* __restrict__ wp,
                                                   float* __restrict__ out) {
    __shared__ float As[16][64];
    __shared__ float Bs[16][64];
    __shared__ int s_any;
    const int t  = threadIdx.x;
    const int tx = t & 15, ty = t >> 4;
    const int m0 = blockIdx.y * 64, o0 = blockIdx.x * 64;
    const int lr = t >> 2, lc = (t & 3) * 4;

    if (t == 0) s_any = 0;
    __syncthreads();
    if (t < 64 && g_flag[m0 + t]) s_any = 1;
    __syncthreads();
    if (!s_any) {   // whole tile's input rows are zero -> outputs are zero spikes
        float4 z = make_float4(0.f, 0.f, 0.f, 0.f);
#pragma unroll
        for (int p = 0; p < 4; p++)
            *(float4*)&out[(size_t)(m0 + lr) * 768 + o0 + (t & 3) * 4 + p * 16] = z;
        return;
    }

    float acc[4][4] = {};
    for (int k0 = 0; k0 < 768; k0 += 16) {
        int    aw = *(const int*)&g_s[m0 + lr][k0 + lc];
        float4 bv = *(const float4*)&wp[(size_t)(o0 + lr) * 768 + k0 + lc];
        __syncthreads();
        As[lc + 0][lr] = (float)((aw << 24) >> 24);
        As[lc + 1][lr] = (float)((aw << 16) >> 24);
        As[lc + 2][lr] = (float)((aw << 8)  >> 24);
        As[lc + 3][lr] = (float)( aw        >> 24);
        Bs[lc + 0][lr] = bv.x; Bs[lc + 1][lr] = bv.y;
        Bs[lc + 2][lr] = bv.z; Bs[lc + 3][lr] = bv.w;
        __syncthreads();
#pragma unroll
        for (int k = 0; k < 16; k++) {
            float4 a = *(const float4*)&As[k][ty * 4];
            float4 b = *(const float4*)&Bs[k][tx * 4];
            float ar[4] = {a.x, a.y, a.z, a.w};
            float br[4] = {b.x, b.y, b.z, b.w};
#pragma unroll
            for (int i = 0; i < 4; i++)
#pragma unroll
                for (int j = 0; j < 4; j++)
                    acc[i][j] = fmaf(ar[i], br[j], acc[i][j]);
        }
    }
#pragma unroll
    for (int i = 0; i < 4; i++) {
        int m = m0 + ty * 4 + i;
#pragma unroll
        for (int j = 0; j < 4; j++) {
            int o = o0 + tx * 4 + j;
            out[(size_t)m * 768 + o] = (float)spike_of(acc[i][j]);
        }
    }
}

// ---------------------------------------------------------------------------
extern "C" void kernel_launch(void* const* d_in, const int* in_sizes, int n_in,
                              void* d_out, int out_size) {
    const float* x      = (const float*)d_in[0];
    const float* w_qkv  = (const float*)d_in[1];
    const float* w_proj = (const float*)d_in[2];
    float* out = (float*)d_out;

    qkv_kernel<<<dim3(36, 128), 256>>>(x, w_qkv);            // 2304/64, 8192/64
    logits_kernel<<<dim3(16, 96), 128>>>();                  // 1024/64, BH
    zero_flags<<<8, 1024>>>();
    softmax_select_kernel<<<dim3(128, 96), 256>>>();         // 1024/8 rows, BH
    proj_kernel<<<dim3(12, 128), 256>>>(w_proj, out);        // 768/64, 8192/64
}

// round 3
// speedup vs baseline: 1.6440x; 1.6440x over previous
#include <cuda_runtime.h>
#include <cuda_bf16.h>
#include <cstdint>

#define B_   8
#define N_   1024
#define C_   768
#define H_   12
#define D_   64
#define BH_  96
#define M_   8192
#define O3_  2304

// Scratch (static __device__ — no allocation in kernel_launch)
__device__ __align__(16) int8_t g_spk[3][BH_][N_][D_];   // q/k/v ternary spikes
__device__ int8_t g_dots[(size_t)BH_ * N_ * N_];         // exact integer logits
__device__ __align__(16) int8_t g_s[M_][C_];             // post-attention spikes
__device__ int    g_flag[M_];                            // per-row spike flag
__device__ __align__(16) __nv_bfloat16 g_xh[M_ * C_];    // x split hi
__device__ __align__(16) __nv_bfloat16 g_xl[M_ * C_];    // x split lo
__device__ __align__(16) __nv_bfloat16 g_wh[O3_ * C_];   // w_qkv split hi
__device__ __align__(16) __nv_bfloat16 g_wl[O3_ * C_];   // w_qkv split lo

#define MARGIN 3e-3f

__device__ __forceinline__ int spike_of(float v) {
    float u = v + 0.5f;                        // replicate reference op order
    return (u >= 1.0f) ? 1 : ((u < 0.0f) ? -1 : 0);
}
__device__ __forceinline__ int8_t spike_sentinel(float v) {
    if (fabsf(v - 0.5f) < MARGIN || fabsf(v + 0.5f) < MARGIN) return (int8_t)2;
    return (v >= 0.5f) ? (int8_t)1 : ((v < -0.5f) ? (int8_t)-1 : (int8_t)0);
}

// ---------------------------------------------------------------------------
// Kernel A0: fp32 -> bf16 hi/lo split of x and w_qkv.
// ---------------------------------------------------------------------------
__global__ void __launch_bounds__(256) convert_kernel(const float* __restrict__ x,
                                                      const float* __restrict__ w) {
    const int stride = gridDim.x * blockDim.x;
    const int nx = M_ * C_ / 4, nw = O3_ * C_ / 4;
    for (int j = blockIdx.x * blockDim.x + threadIdx.x; j < nx; j += stride) {
        float4 v = ((const float4*)x)[j];
        float vv[4] = {v.x, v.y, v.z, v.w};
        __nv_bfloat16 h[4], l[4];
#pragma unroll
        for (int i = 0; i < 4; i++) {
            h[i] = __float2bfloat16(vv[i]);
            l[i] = __float2bfloat16(vv[i] - __bfloat162float(h[i]));
        }
        __nv_bfloat162 p0, p1, q0, q1;
        p0.x = h[0]; p0.y = h[1]; p1.x = h[2]; p1.y = h[3];
        q0.x = l[0]; q0.y = l[1]; q1.x = l[2]; q1.y = l[3];
        ((__nv_bfloat162*)g_xh)[2*j]     = p0;
        ((__nv_bfloat162*)g_xh)[2*j + 1] = p1;
        ((__nv_bfloat162*)g_xl)[2*j]     = q0;
        ((__nv_bfloat162*)g_xl)[2*j + 1] = q1;
    }
    for (int j = blockIdx.x * blockDim.x + threadIdx.x; j < nw; j += stride) {
        float4 v = ((const float4*)w)[j];
        float vv[4] = {v.x, v.y, v.z, v.w};
        __nv_bfloat16 h[4], l[4];
#pragma unroll
        for (int i = 0; i < 4; i++) {
            h[i] = __float2bfloat16(vv[i]);
            l[i] = __float2bfloat16(vv[i] - __bfloat162float(h[i]));
        }
        __nv_bfloat162 p0, p1, q0, q1;
        p0.x = h[0]; p0.y = h[1]; p1.x = h[2]; p1.y = h[3];
        q0.x = l[0]; q0.y = l[1]; q1.x = l[2]; q1.y = l[3];
        ((__nv_bfloat162*)g_wh)[2*j]     = p0;
        ((__nv_bfloat162*)g_wh)[2*j + 1] = p1;
        ((__nv_bfloat162*)g_wl)[2*j]     = q0;
        ((__nv_bfloat162*)g_wl)[2*j + 1] = q1;
    }
}

// ---------------------------------------------------------------------------
// Kernel A1: QKV GEMM via warp mma.sync bf16 (hi*hi + hi*lo + lo*hi, f32 acc).
// 128x128 tile, BK=32, 8 warps (4M x 2N), warp tile 32x64.
// ---------------------------------------------------------------------------
#define ASTRIDE 20   // int words per smem row (16 used + 4 pad -> conflict-free)

__device__ __forceinline__ void mma_bf16(float* c, const int* a, const int* b) {
    asm volatile("mma.sync.aligned.m16n8k16.row.col.f32.bf16.bf16.f32 "
        "{%0,%1,%2,%3}, {%4,%5,%6,%7}, {%8,%9}, {%0,%1,%2,%3};"
        : "+f"(c[0]), "+f"(c[1]), "+f"(c[2]), "+f"(c[3])
        : "r"(a[0]), "r"(a[1]), "r"(a[2]), "r"(a[3]), "r"(b[0]), "r"(b[1]));
}

__global__ void __launch_bounds__(256) qkv_mma_kernel() {
    __shared__ int sAh[128 * ASTRIDE], sAl[128 * ASTRIDE];
    __shared__ int sBh[128 * ASTRIDE], sBl[128 * ASTRIDE];
    const int t = threadIdx.x, lane = t & 31, wid = t >> 5;
    const int g = lane >> 2, tig = lane & 3;
    const int warpM = wid & 3, warpN = wid >> 2;
    const int o0 = blockIdx.x * 128, m0 = blockIdx.y * 128;

    float acc[2][8][4] = {};

    const int lrow = t >> 1;             // 128 rows, 2 threads per row
    const int lq   = (t & 1) * 2;        // int4 index 0/2 (each thread: 2 int4)

    for (int k0 = 0; k0 < 768; k0 += 32) {
        __syncthreads();
        {
            size_t ga = (size_t)(m0 + lrow) * C_ + k0 + lq * 8;
            size_t gb = (size_t)(o0 + lrow) * C_ + k0 + lq * 8;
            int w0 = lrow * ASTRIDE + lq * 4;
            *(int4*)&sAh[w0]     = *(const int4*)(g_xh + ga);
            *(int4*)&sAh[w0 + 4] = *(const int4*)(g_xh + ga + 8);
            *(int4*)&sAl[w0]     = *(const int4*)(g_xl + ga);
            *(int4*)&sAl[w0 + 4] = *(const int4*)(g_xl + ga + 8);
            *(int4*)&sBh[w0]     = *(const int4*)(g_wh + gb);
            *(int4*)&sBh[w0 + 4] = *(const int4*)(g_wh + gb + 8);
            *(int4*)&sBl[w0]     = *(const int4*)(g_wl + gb);
            *(int4*)&sBl[w0 + 4] = *(const int4*)(g_wl + gb + 8);
        }
        __syncthreads();
#pragma unroll
        for (int ks = 0; ks < 2; ks++) {
            int ah[2][4], al[2][4];
#pragma unroll
            for (int mi = 0; mi < 2; mi++) {
                int r0 = (warpM * 32 + mi * 16 + g) * ASTRIDE + ks * 8 + tig;
                ah[mi][0] = sAh[r0];
                ah[mi][1] = sAh[r0 + 8 * ASTRIDE];
                ah[mi][2] = sAh[r0 + 4];
                ah[mi][3] = sAh[r0 + 8 * ASTRIDE + 4];
                al[mi][0] = sAl[r0];
                al[mi][1] = sAl[r0 + 8 * ASTRIDE];
                al[mi][2] = sAl[r0 + 4];
                al[mi][3] = sAl[r0 + 8 * ASTRIDE + 4];
            }
#pragma unroll
            for (int ni = 0; ni < 8; ni++) {
                int rb = (warpN * 64 + ni * 8 + g) * ASTRIDE + ks * 8 + tig;
                int bhf[2] = { sBh[rb], sBh[rb + 4] };
                int blf[2] = { sBl[rb], sBl[rb + 4] };
#pragma unroll
                for (int mi = 0; mi < 2; mi++) {
                    mma_bf16(acc[mi][ni], ah[mi], bhf);
                    mma_bf16(acc[mi][ni], ah[mi], blf);
                    mma_bf16(acc[mi][ni], al[mi], bhf);
                }
            }
        }
    }

    // Epilogue: spikes with uncertainty sentinel, direct to g_spk
    const int tt = o0 / 768;
    const int h0 = ((o0 % 768) >> 6) + warpN;
    const int bh = (m0 >> 10) * H_ + h0;
    const int nb = (m0 & 1023) + warpM * 32;
#pragma unroll
    for (int mi = 0; mi < 2; mi++) {
        int n1 = nb + mi * 16 + g;
#pragma unroll
        for (int ni = 0; ni < 8; ni++) {
            int d = ni * 8 + tig * 2;
            char2 v0, v1;
            v0.x = spike_sentinel(acc[mi][ni][0]);
            v0.y = spike_sentinel(acc[mi][ni][1]);
            v1.x = spike_sentinel(acc[mi][ni][2]);
            v1.y = spike_sentinel(acc[mi][ni][3]);
            *(char2*)&g_spk[tt][bh][n1][d]     = v0;
            *(char2*)&g_spk[tt][bh][n1 + 8][d] = v1;
        }
    }
}

// ---------------------------------------------------------------------------
// Kernel A2: fixup — recompute sentinel elems with exact fp32 warp-dots.
// ---------------------------------------------------------------------------
__global__ void __launch_bounds__(256) fixup_kernel(const float* __restrict__ x,
                                                    const float* __restrict__ w) {
    const int lane = threadIdx.x & 31;
    const int warps_total = (gridDim.x * blockDim.x) >> 5;
    const int gw = (blockIdx.x * blockDim.x + threadIdx.x) >> 5;
    int8_t* gs = &g_spk[0][0][0][0];
    const int total4 = (3 * BH_ * N_ * D_) / 16;   // int4 count, multiple of 32

    for (int base = gw * 32; base < total4; base += warps_total * 32) {
        int i4 = base + lane;
        int4 v = ((const int4*)gs)[i4];
        int words[4] = {v.x, v.y, v.z, v.w};
        unsigned flag = 0;
#pragma unroll
        for (int wj = 0; wj < 4; wj++)
#pragma unroll
            for (int bj = 0; bj < 4; bj++)
                if (((words[wj] >> (8 * bj)) & 0xff) == 2) flag |= 1u << (wj * 4 + bj);

        unsigned any = __ballot_sync(0xffffffffu, flag != 0);
        while (any) {
            int src = __ffs(any) - 1;
            any &= any - 1;
            unsigned f = __shfl_sync(0xffffffffu, flag, src);
            int bi4 = __shfl_sync(0xffffffffu, i4, src);
            while (f) {
                int bidx = __ffs(f) - 1;
                f &= f - 1;
                size_t bi = (size_t)bi4 * 16 + bidx;
                int d = (int)(bi & 63);
                int nn = (int)((bi >> 6) & 1023);
                int hb = (int)(bi >> 16);           // tt*96 + bh
                int tt = hb / BH_, bh = hb - tt * BH_;
                int m = (bh / H_) * N_ + nn;
                int o = tt * 768 + (bh % H_) * 64 + d;
                float s = 0.0f;
                for (int c = lane; c < C_; c += 32)
                    s += x[(size_t)m * C_ + c] * w[(size_t)o * C_ + c];
#pragma unroll
                for (int off = 16; off; off >>= 1)
                    s += __shfl_xor_sync(0xffffffffu, s, off);
                if (lane == 0) gs[bi] = (int8_t)spike_of(s);
            }
        }
    }
}

// ---------------------------------------------------------------------------
// Kernel B1: exact integer attention logits via s8 IMMA.
// ---------------------------------------------------------------------------
__global__ void __launch_bounds__(128) logits_kernel() {
    __shared__ int8_t ssq[64][64];
    __shared__ int8_t ssk[64][64];
    const int t = threadIdx.x;
    const int lane = t & 31, wrp = t >> 5;
    const int gid = lane >> 2, tig = lane & 3;
    const int bh = blockIdx.y, n0 = blockIdx.x * 64;

    {
        const int4* src = (const int4*)&g_spk[0][bh][n0][0];
        int4* dst = (int4*)&ssq[0][0];
        dst[t] = src[t]; dst[t + 128] = src[t + 128];
    }
    __syncthreads();

    int afr[2][4];
#pragma unroll
    for (int ks = 0; ks < 2; ks++) {
        int r = wrp * 16 + gid;
        afr[ks][0] = *(const int*)&ssq[r    ][ks * 32 + tig * 4];
        afr[ks][1] = *(const int*)&ssq[r + 8][ks * 32 + tig * 4];
        afr[ks][2] = *(const int*)&ssq[r    ][ks * 32 + 16 + tig * 4];
        afr[ks][3] = *(const int*)&ssq[r + 8][ks * 32 + 16 + tig * 4];
    }

    const size_t base = (size_t)bh * N_ * N_;
    for (int mc = 0; mc < 16; mc++) {
        __syncthreads();
        {
            const int4* src = (const int4*)&g_spk[1][bh][mc * 64][0];
            int4* dst = (int4*)&ssk[0][0];
            dst[t] = src[t]; dst[t + 128] = src[t + 128];
        }
        __syncthreads();
#pragma unroll
        for (int c = 0; c < 8; c++) {
            int c0 = 0, c1 = 0, c2 = 0, c3 = 0;
#pragma unroll
            for (int ks = 0; ks < 2; ks++) {
                int b0 = *(const int*)&ssk[c * 8 + gid][ks * 32 + tig * 4];
                int b1 = *(const int*)&ssk[c * 8 + gid][ks * 32 + 16 + tig * 4];
                asm volatile(
                    "mma.sync.aligned.m16n8k32.row.col.s32.s8.s8.s32 "
                    "{%0,%1,%2,%3}, {%4,%5,%6,%7}, {%8,%9}, {%0,%1,%2,%3};"
                    : "+r"(c0), "+r"(c1), "+r"(c2), "+r"(c3)
                    : "r"(afr[ks][0]), "r"(afr[ks][1]), "r"(afr[ks][2]), "r"(afr[ks][3]),
                      "r"(b0), "r"(b1));
            }
            int row = n0 + wrp * 16 + gid;
            int col = mc * 64 + c * 8 + tig * 2;
            char2 lo; lo.x = (char)c0; lo.y = (char)c1;
            char2 hi; hi.x = (char)c2; hi.y = (char)c3;
            *(char2*)&g_dots[base + (size_t)row * N_ + col]       = lo;
            *(char2*)&g_dots[base + (size_t)(row + 8) * N_ + col] = hi;
        }
    }
}

__global__ void zero_flags() {
    int i = blockIdx.x * blockDim.x + threadIdx.x;
    if (i < M_) g_flag[i] = 0;
}

// ---------------------------------------------------------------------------
// Kernel B2: softmax decision + v-row select.
// ---------------------------------------------------------------------------
__global__ void __launch_bounds__(256) softmax_select_kernel() {
    const int t = threadIdx.x, lane = t & 31, wrp = t >> 5;
    const int bh = blockIdx.y;
    const int n = blockIdx.x * 8 + wrp;
    const int b = bh / H_, h = bh - b * H_;

    const int8_t* row = &g_dots[(size_t)bh * N_ * N_ + (size_t)n * N_];
    int4 v0 = ((const int4*)row)[lane];
    int4 v1 = ((const int4*)row)[lane + 32];
    int words[8] = {v0.x, v0.y, v0.z, v0.w, v1.x, v1.y, v1.z, v1.w};

    int lmax = -1000;
#pragma unroll
    for (int wi = 0; wi < 8; wi++)
#pragma unroll
        for (int j = 0; j < 4; j++) {
            int val = (words[wi] << (24 - 8 * j)) >> 24;
            lmax = max(lmax, val);
        }
#pragma unroll
    for (int off = 16; off; off >>= 1)
        lmax = max(lmax, __shfl_xor_sync(0xffffffffu, lmax, off));

    float s = 0.0f;
    int larg = 0x7fffffff;
#pragma unroll
    for (int wi = 0; wi < 8; wi++) {
        int colbase = (wi < 4) ? (lane * 16 + wi * 4) : (512 + lane * 16 + (wi - 4) * 4);
#pragma unroll
        for (int j = 0; j < 4; j++) {
            int val = (words[wi] << (24 - 8 * j)) >> 24;
            s += expf(0.125f * (float)(val - lmax));
            if (val == lmax) larg = min(larg, colbase + j);
        }
    }
#pragma unroll
    for (int off = 16; off; off >>= 1) {
        s    += __shfl_xor_sync(0xffffffffu, s, off);
        larg  = min(larg, __shfl_xor_sync(0xffffffffu, larg, off));
    }

    float p = 1.0f / s;
    bool spk = (p + 0.5f) >= 1.0f;

    int* dst = (int*)&g_s[b * N_ + n][h * D_];
    if (spk) {
        const int* src = (const int*)&g_spk[2][bh][larg][0];
        if (lane < 16) dst[lane] = src[lane];
        if (lane == 0) g_flag[b * N_ + n] = 1;
    } else {
        if (lane < 16) dst[lane] = 0;
    }
}

// ---------------------------------------------------------------------------
// Kernel C: output projection (fp32 exact) + final IF, zero-tile skip.
// ---------------------------------------------------------------------------
__global__ void __launch_bounds__(256) proj_kernel(const float* __restrict__ wp,
                                                   float* __restrict__ out) {
    __shared__ float As[16][64];
    __shared__ float Bs[16][64];
    __shared__ int s_any;
    const int t = threadIdx.x;
    const int tx = t & 15, ty = t >> 4;
    const int m0 = blockIdx.y * 64, o0 = blockIdx.x * 64;
    const int lr = t >> 2, lc = (t & 3) * 4;

    if (t == 0) s_any = 0;
    __syncthreads();
    if (t < 64 && g_flag[m0 + t]) s_any = 1;
    __syncthreads();
    if (!s_any) {
        float4 z = make_float4(0.f, 0.f, 0.f, 0.f);
#pragma unroll
        for (int p = 0; p < 4; p++)
            *(float4*)&out[(size_t)(m0 + lr) * 768 + o0 + (t & 3) * 4 + p * 16] = z;
        return;
    }

    float acc[4][4] = {};
    for (int k0 = 0; k0 < 768; k0 += 16) {
        int    aw = *(const int*)&g_s[m0 + lr][k0 + lc];
        float4 bv = *(const float4*)&wp[(size_t)(o0 + lr) * 768 + k0 + lc];
        __syncthreads();
        As[lc + 0][lr] = (float)((aw << 24) >> 24);
        As[lc + 1][lr] = (float)((aw << 16) >> 24);
        As[lc + 2][lr] = (float)((aw << 8)  >> 24);
        As[lc + 3][lr] = (float)( aw        >> 24);
        Bs[lc + 0][lr] = bv.x; Bs[lc + 1][lr] = bv.y;
        Bs[lc + 2][lr] = bv.z; Bs[lc + 3][lr] = bv.w;
        __syncthreads();
#pragma unroll
        for (int k = 0; k < 16; k++) {
            float4 a = *(const float4*)&As[k][ty * 4];
            float4 b = *(const float4*)&Bs[k][tx * 4];
            float ar[4] = {a.x, a.y, a.z, a.w};
            float br[4] = {b.x, b.y, b.z, b.w};
#pragma unroll
            for (int i = 0; i < 4; i++)
#pragma unroll
                for (int j = 0; j < 4; j++)
                    acc[i][j] = fmaf(ar[i], br[j], acc[i][j]);
        }
    }
#pragma unroll
    for (int i = 0; i < 4; i++) {
        int m = m0 + ty * 4 + i;
#pragma unroll
        for (int j = 0; j < 4; j++) {
            int o = o0 + tx * 4 + j;
            out[(size_t)m * 768 + o] = (float)spike_of(acc[i][j]);
        }
    }
}

// ---------------------------------------------------------------------------
extern "C" void kernel_launch(void* const* d_in, const int* in_sizes, int n_in,
                              void* d_out, int out_size) {
    const float* x      = (const float*)d_in[0];
    const float* w_qkv  = (const float*)d_in[1];
    const float* w_proj = (const float*)d_in[2];
    float* out = (float*)d_out;

    convert_kernel<<<960, 256>>>(x, w_qkv);
    qkv_mma_kernel<<<dim3(18, 64), 256>>>();
    fixup_kernel<<<1024, 256>>>(x, w_qkv);
    logits_kernel<<<dim3(16, 96), 128>>>();
    zero_flags<<<8, 1024>>>();
    softmax_select_kernel<<<dim3(128, 96), 256>>>();
    proj_kernel<<<dim3(12, 128), 256>>>(w_proj, out);
}

// round 4
// speedup vs baseline: 2.2133x; 1.3463x over previous
#include <cuda_runtime.h>
#include <cuda_bf16.h>
#include <cstdint>

#define B_   8
#define N_   1024
#define C_   768
#define H_   12
#define D_   64
#define BH_  96
#define M_   8192
#define O3_  2304
#define FIXCAP (1 << 21)

// Scratch (static __device__ — no allocation in kernel_launch)
__device__ __align__(16) int8_t g_spk[3][BH_][N_][D_];   // q/k/v ternary spikes
__device__ __align__(16) int8_t g_s[M_][C_];             // post-attention spikes
__device__ int    g_flag[M_];                            // per-row spike flag
__device__ int    g_nfix;                                // uncertain-element count
__device__ int    g_fix_list[FIXCAP];                    // packed m*2304+o
__device__ __align__(16) __nv_bfloat16 g_xh[M_ * C_];    // x split hi
__device__ __align__(16) __nv_bfloat16 g_xl[M_ * C_];    // x split lo
__device__ __align__(16) __nv_bfloat16 g_wh[O3_ * C_];   // w_qkv split hi
__device__ __align__(16) __nv_bfloat16 g_wl[O3_ * C_];   // w_qkv split lo

#define MARGIN 3e-3f

__device__ __forceinline__ int spike_of(float v) {
    float u = v + 0.5f;                        // replicate reference op order
    return (u >= 1.0f) ? 1 : ((u < 0.0f) ? -1 : 0);
}

// ---------------------------------------------------------------------------
// Kernel 0: zero flags + fixup counter (graph replays need deterministic init)
// ---------------------------------------------------------------------------
__global__ void init_kernel() {
    int i = blockIdx.x * blockDim.x + threadIdx.x;
    if (i < M_) g_flag[i] = 0;
    if (i == 0) g_nfix = 0;
}

// ---------------------------------------------------------------------------
// Kernel A0: fp32 -> bf16 hi/lo split of x and w_qkv.
// ---------------------------------------------------------------------------
__global__ void __launch_bounds__(256) convert_kernel(const float* __restrict__ x,
                                                      const float* __restrict__ w) {
    const int stride = gridDim.x * blockDim.x;
    const int nx = M_ * C_ / 4, nw = O3_ * C_ / 4;
    for (int j = blockIdx.x * blockDim.x + threadIdx.x; j < nx; j += stride) {
        float4 v = ((const float4*)x)[j];
        float vv[4] = {v.x, v.y, v.z, v.w};
        __nv_bfloat16 h[4], l[4];
#pragma unroll
        for (int i = 0; i < 4; i++) {
            h[i] = __float2bfloat16(vv[i]);
            l[i] = __float2bfloat16(vv[i] - __bfloat162float(h[i]));
        }
        __nv_bfloat162 p0, p1, q0, q1;
        p0.x = h[0]; p0.y = h[1]; p1.x = h[2]; p1.y = h[3];
        q0.x = l[0]; q0.y = l[1]; q1.x = l[2]; q1.y = l[3];
        ((__nv_bfloat162*)g_xh)[2*j]     = p0;
        ((__nv_bfloat162*)g_xh)[2*j + 1] = p1;
        ((__nv_bfloat162*)g_xl)[2*j]     = q0;
        ((__nv_bfloat162*)g_xl)[2*j + 1] = q1;
    }
    for (int j = blockIdx.x * blockDim.x + threadIdx.x; j < nw; j += stride) {
        float4 v = ((const float4*)w)[j];
        float vv[4] = {v.x, v.y, v.z, v.w};
        __nv_bfloat16 h[4], l[4];
#pragma unroll
        for (int i = 0; i < 4; i++) {
            h[i] = __float2bfloat16(vv[i]);
            l[i] = __float2bfloat16(vv[i] - __bfloat162float(h[i]));
        }
        __nv_bfloat162 p0, p1, q0, q1;
        p0.x = h[0]; p0.y = h[1]; p1.x = h[2]; p1.y = h[3];
        q0.x = l[0]; q0.y = l[1]; q1.x = l[2]; q1.y = l[3];
        ((__nv_bfloat162*)g_wh)[2*j]     = p0;
        ((__nv_bfloat162*)g_wh)[2*j + 1] = p1;
        ((__nv_bfloat162*)g_wl)[2*j]     = q0;
        ((__nv_bfloat162*)g_wl)[2*j + 1] = q1;
    }
}

// ---------------------------------------------------------------------------
// Kernel A1: QKV GEMM, mma.sync bf16 split, cp.async double-buffered.
// 128x128 tile, BK=32, 8 warps (4M x 2N), warp tile 32x64.
// Dynamic smem: 2 stages x 4 arrays x (128 rows x 80B) = 81920 B.
// ---------------------------------------------------------------------------
#define ASTRIDE 20               // ints per smem row (16 data + 4 pad)
#define ARR_B   10240            // bytes per array per stage
#define STG_B   40960            // bytes per stage
#define QKV_DSMEM 81920

__device__ __forceinline__ void mma_bf16(float* c, const int* a, const int* b) {
    asm volatile("mma.sync.aligned.m16n8k16.row.col.f32.bf16.bf16.f32 "
        "{%0,%1,%2,%3}, {%4,%5,%6,%7}, {%8,%9}, {%0,%1,%2,%3};"
        : "+f"(c[0]), "+f"(c[1]), "+f"(c[2]), "+f"(c[3])
        : "r"(a[0]), "r"(a[1]), "r"(a[2]), "r"(a[3]), "r"(b[0]), "r"(b[1]));
}

__global__ void __launch_bounds__(256) qkv_mma_kernel() {
    extern __shared__ char dyn[];
    uint32_t sbase;
    asm("{ .reg .u64 tmp; cvta.to.shared.u64 tmp, %1; cvt.u32.u64 %0, tmp; }"
        : "=r"(sbase) : "l"(dyn));
    const int t = threadIdx.x, lane = t & 31, wid = t >> 5;
    const int g = lane >> 2, tig = lane & 3;
    const int warpM = wid & 3, warpN = wid >> 2;
    const int o0 = blockIdx.x * 128, m0 = blockIdx.y * 128;

    float acc[2][8][4] = {};

    // prefetch helper: thread handles chunks t and t+256 of each array
#define PREFETCH(st, k0) do {                                                  \
    int _s = (st) * STG_B;                                                     \
    _Pragma("unroll")                                                          \
    for (int _c = 0; _c < 2; _c++) {                                           \
        int ch = t + _c * 256;                                                 \
        int row = ch >> 2, qi = ch & 3;                                        \
        uint32_t doff = (uint32_t)(row * 80 + qi * 16);                        \
        size_t ga = (size_t)(m0 + row) * C_ + (k0) + qi * 8;                   \
        size_t gb = (size_t)(o0 + row) * C_ + (k0) + qi * 8;                   \
        asm volatile("cp.async.cg.shared.global [%0], [%1], 16;"               \
                     :: "r"(sbase + _s + doff), "l"(g_xh + ga));               \
        asm volatile("cp.async.cg.shared.global [%0], [%1], 16;"               \
                     :: "r"(sbase + _s + ARR_B + doff), "l"(g_xl + ga));       \
        asm volatile("cp.async.cg.shared.global [%0], [%1], 16;"               \
                     :: "r"(sbase + _s + 2 * ARR_B + doff), "l"(g_wh + gb));   \
        asm volatile("cp.async.cg.shared.global [%0], [%1], 16;"               \
                     :: "r"(sbase + _s + 3 * ARR_B + doff), "l"(g_wl + gb));   \
    } } while (0)

    PREFETCH(0, 0);
    asm volatile("cp.async.commit_group;");

    for (int it = 0; it < 24; it++) {
        if (it + 1 < 24) {
            PREFETCH((it + 1) & 1, (it + 1) * 32);
            asm volatile("cp.async.commit_group;");
            asm volatile("cp.async.wait_group 1;");
        } else {
            asm volatile("cp.async.wait_group 0;");
        }
        __syncthreads();

        const int* pAh = (const int*)(dyn + (it & 1) * STG_B);
        const int* pAl = (const int*)(dyn + (it & 1) * STG_B + ARR_B);
        const int* pBh = (const int*)(dyn + (it & 1) * STG_B + 2 * ARR_B);
        const int* pBl = (const int*)(dyn + (it & 1) * STG_B + 3 * ARR_B);
#pragma unroll
        for (int ks = 0; ks < 2; ks++) {
            int ah[2][4], al[2][4];
#pragma unroll
            for (int mi = 0; mi < 2; mi++) {
                int r0 = (warpM * 32 + mi * 16 + g) * ASTRIDE + ks * 8 + tig;
                ah[mi][0] = pAh[r0];
                ah[mi][1] = pAh[r0 + 8 * ASTRIDE];
                ah[mi][2] = pAh[r0 + 4];
                ah[mi][3] = pAh[r0 + 8 * ASTRIDE + 4];
                al[mi][0] = pAl[r0];
                al[mi][1] = pAl[r0 + 8 * ASTRIDE];
                al[mi][2] = pAl[r0 + 4];
                al[mi][3] = pAl[r0 + 8 * ASTRIDE + 4];
            }
#pragma unroll
            for (int ni = 0; ni < 8; ni++) {
                int rb = (warpN * 64 + ni * 8 + g) * ASTRIDE + ks * 8 + tig;
                int bhf[2] = { pBh[rb], pBh[rb + 4] };
                int blf[2] = { pBl[rb], pBl[rb + 4] };
#pragma unroll
                for (int mi = 0; mi < 2; mi++) {
                    mma_bf16(acc[mi][ni], ah[mi], bhf);
                    mma_bf16(acc[mi][ni], ah[mi], blf);
                    mma_bf16(acc[mi][ni], al[mi], bhf);
                }
            }
        }
        __syncthreads();
    }

    // Epilogue: provisional spikes + warp-aggregated push of uncertain coords
    const int tt = o0 / 768;
    const int h0 = ((o0 % 768) >> 6) + warpN;
    const int bh = (m0 >> 10) * H_ + h0;
    const int nb = (m0 & 1023) + warpM * 32;
#pragma unroll
    for (int mi = 0; mi < 2; mi++) {
#pragma unroll
        for (int ni = 0; ni < 8; ni++) {
            int8_t sv[4];
#pragma unroll
            for (int e = 0; e < 4; e++) {
                float v = acc[mi][ni][e];
                sv[e] = (int8_t)spike_of(v);
                bool unc = (fabsf(v - 0.5f) < MARGIN) || (fabsf(v + 0.5f) < MARGIN);
                unsigned msk = __ballot_sync(0xffffffffu, unc);
                if (msk) {
                    int ldr = __ffs(msk) - 1;
                    int base = 0;
                    if (lane == ldr) base = atomicAdd(&g_nfix, __popc(msk));
                    base = __shfl_sync(0xffffffffu, base, ldr);
                    if (unc) {
                        int mg = m0 + warpM * 32 + mi * 16 + g + ((e >> 1) ? 8 : 0);
                        int og = o0 + warpN * 64 + ni * 8 + tig * 2 + (e & 1);
                        int pos = base + __popc(msk & ((1u << lane) - 1));
                        if (pos < FIXCAP) g_fix_list[pos] = mg * O3_ + og;
                    }
                }
            }
            int n1 = nb + mi * 16 + g;
            int d = ni * 8 + tig * 2;
            char2 v0, v1;
            v0.x = sv[0]; v0.y = sv[1];
            v1.x = sv[2]; v1.y = sv[3];
            *(char2*)&g_spk[tt][bh][n1][d]     = v0;
            *(char2*)&g_spk[tt][bh][n1 + 8][d] = v1;
        }
    }
}

// ---------------------------------------------------------------------------
// Kernel A2: fixup — exact fp32 warp-dots for listed uncertain elements.
// ---------------------------------------------------------------------------
__global__ void __launch_bounds__(256) fixup_kernel(const float* __restrict__ x,
                                                    const float* __restrict__ w) {
    const int lane = threadIdx.x & 31;
    const int gw = (blockIdx.x * blockDim.x + threadIdx.x) >> 5;
    const int nw = (gridDim.x * blockDim.x) >> 5;
    int nfix = g_nfix;
    if (nfix > FIXCAP) nfix = FIXCAP;

    for (int i = gw; i < nfix; i += nw) {
        int code = g_fix_list[i];
        int m = code / O3_;
        int o = code - m * O3_;
        float s = 0.0f;
        for (int c = lane; c < C_; c += 32)
            s += x[(size_t)m * C_ + c] * w[(size_t)o * C_ + c];
#pragma unroll
        for (int off = 16; off; off >>= 1)
            s += __shfl_xor_sync(0xffffffffu, s, off);
        if (lane == 0) {
            int tt = o / 768, rem = o - tt * 768;
            g_spk[tt][(m >> 10) * H_ + (rem >> 6)][m & 1023][rem & 63] =
                (int8_t)spike_of(s);
        }
    }
}

// ---------------------------------------------------------------------------
// Kernel B: FUSED attention — s8 IMMA logits into smem, then per-row
// softmax decision + v-row select, no gmem round-trip of the dot matrix.
// Block = (bh, 64 q-rows), 128 threads. Dynamic smem:
//   ssq 4KB @0, ssk 4KB @4096, sdots 64 rows x 1040B @8192 -> 74752 B.
// ---------------------------------------------------------------------------
#define ATTN_DSMEM (8192 + 64 * 1040)

__global__ void __launch_bounds__(128) attn_kernel() {
    extern __shared__ char dyn[];
    char* ssq = dyn;
    char* ssk = dyn + 4096;
    char* sd  = dyn + 8192;
    const int t = threadIdx.x;
    const int lane = t & 31, wrp = t >> 5;
    const int gid = lane >> 2, tig = lane & 3;
    const int bh = blockIdx.y, n0 = blockIdx.x * 64;
    const int b = bh / H_, h = bh - b * H_;

    {
        const int4* src = (const int4*)&g_spk[0][bh][n0][0];
        int4* dst = (int4*)ssq;
        dst[t] = src[t]; dst[t + 128] = src[t + 128];
    }
    __syncthreads();

    int afr[2][4];
#pragma unroll
    for (int ks = 0; ks < 2; ks++) {
        int r = wrp * 16 + gid;
        afr[ks][0] = *(const int*)(ssq + r * 64 + ks * 32 + tig * 4);
        afr[ks][1] = *(const int*)(ssq + (r + 8) * 64 + ks * 32 + tig * 4);
        afr[ks][2] = *(const int*)(ssq + r * 64 + ks * 32 + 16 + tig * 4);
        afr[ks][3] = *(const int*)(ssq + (r + 8) * 64 + ks * 32 + 16 + tig * 4);
    }

    for (int mc = 0; mc < 16; mc++) {
        __syncthreads();
        {
            const int4* src = (const int4*)&g_spk[1][bh][mc * 64][0];
            int4* dst = (int4*)ssk;
            dst[t] = src[t]; dst[t + 128] = src[t + 128];
        }
        __syncthreads();
#pragma unroll
        for (int c = 0; c < 8; c++) {
            int c0 = 0, c1 = 0, c2 = 0, c3 = 0;
#pragma unroll
            for (int ks = 0; ks < 2; ks++) {
                int b0 = *(const int*)(ssk + (c * 8 + gid) * 64 + ks * 32 + tig * 4);
                int b1 = *(const int*)(ssk + (c * 8 + gid) * 64 + ks * 32 + 16 + tig * 4);
                asm volatile(
                    "mma.sync.aligned.m16n8k32.row.col.s32.s8.s8.s32 "
                    "{%0,%1,%2,%3}, {%4,%5,%6,%7}, {%8,%9}, {%0,%1,%2,%3};"
                    : "+r"(c0), "+r"(c1), "+r"(c2), "+r"(c3)
                    : "r"(afr[ks][0]), "r"(afr[ks][1]), "r"(afr[ks][2]), "r"(afr[ks][3]),
                      "r"(b0), "r"(b1));
            }
            int row = wrp * 16 + gid;
            int col = mc * 64 + c * 8 + tig * 2;
            char2 lo; lo.x = (char)c0; lo.y = (char)c1;
            char2 hi; hi.x = (char)c2; hi.y = (char)c3;
            *(char2*)(sd + row * 1040 + col)       = lo;
            *(char2*)(sd + (row + 8) * 1040 + col) = hi;
        }
    }
    __syncthreads();

    // Phase 2: each warp reduces 16 rows
    for (int r = 0; r < 16; r++) {
        const int row = wrp * 16 + r;
        const char* rp = sd + row * 1040;
        int4 v0 = ((const int4*)rp)[lane];
        int4 v1 = ((const int4*)rp)[lane + 32];
        int words[8] = {v0.x, v0.y, v0.z, v0.w, v1.x, v1.y, v1.z, v1.w};

        // SIMD byte max
        int mxw = words[0];
#pragma unroll
        for (int wi = 1; wi < 8; wi++) mxw = __vmaxs4(mxw, words[wi]);
#pragma unroll
        for (int off = 16; off; off >>= 1)
            mxw = __vmaxs4(mxw, __shfl_xor_sync(0xffffffffu, mxw, off));
        int lmax = max(max((mxw << 24) >> 24, (mxw << 16) >> 24),
                       max((mxw << 8) >> 24,  mxw >> 24));

        // cheap reject: count elements >= lmax - 8 (each contributes >= e^-1)
        int t8 = lmax - 8;
        int tspl = (t8 & 0xff) * 0x01010101;
        int cnt = 0;
#pragma unroll
        for (int wi = 0; wi < 8; wi++)
            cnt += __popc(__vcmpges4(words[wi], tspl));
#pragma unroll
        for (int off = 16; off; off >>= 1)
            cnt += __shfl_xor_sync(0xffffffffu, cnt, off);

        int* dst = (int*)&g_s[b * N_ + n0 + row][h * D_];
        if (cnt >= 32) {        // >= 4 elems -> s >= 1 + 3/e = 2.10 > 2: no spike
            if (lane < 16) dst[lane] = 0;
            continue;
        }

        // exact path (rare): argmax + precise expf sum, matches reference math
        float s = 0.0f;
        int larg = 0x7fffffff;
#pragma unroll
        for (int wi = 0; wi < 8; wi++) {
            int colbase = (wi < 4) ? (lane * 16 + wi * 4)
                                   : (512 + lane * 16 + (wi - 4) * 4);
#pragma unroll
            for (int j = 0; j < 4; j++) {
                int val = (words[wi] << (24 - 8 * j)) >> 24;
                s += expf(0.125f * (float)(val - lmax));
                if (val == lmax) larg = min(larg, colbase + j);
            }
        }
#pragma unroll
        for (int off = 16; off; off >>= 1) {
            s    += __shfl_xor_sync(0xffffffffu, s, off);
            larg  = min(larg, __shfl_xor_sync(0xffffffffu, larg, off));
        }
        float p = 1.0f / s;
        bool spk = (p + 0.5f) >= 1.0f;
        if (spk) {
            const int* src = (const int*)&g_spk[2][bh][larg][0];
            if (lane < 16) dst[lane] = src[lane];
            if (lane == 0) g_flag[b * N_ + n0 + row] = 1;
        } else {
            if (lane < 16) dst[lane] = 0;
        }
    }
}

// ---------------------------------------------------------------------------
// Kernel C: output projection (fp32 exact) + final IF, zero-tile skip.
// ---------------------------------------------------------------------------
__global__ void __launch_bounds__(256) proj_kernel(const float* __restrict__ wp,
                                                   float* __restrict__ out) {
    __shared__ float As[16][64];
    __shared__ float Bs[16][64];
    __shared__ int s_any;
    const int t = threadIdx.x;
    const int tx = t & 15, ty = t >> 4;
    const int m0 = blockIdx.y * 64, o0 = blockIdx.x * 64;
    const int lr = t >> 2, lc = (t & 3) * 4;

    if (t == 0) s_any = 0;
    __syncthreads();
    if (t < 64 && g_flag[m0 + t]) s_any = 1;
    __syncthreads();
    if (!s_any) {
        float4 z = make_float4(0.f, 0.f, 0.f, 0.f);
#pragma unroll
        for (int p = 0; p < 4; p++)
            *(float4*)&out[(size_t)(m0 + lr) * 768 + o0 + (t & 3) * 4 + p * 16] = z;
        return;
    }

    float acc[4][4] = {};
    for (int k0 = 0; k0 < 768; k0 += 16) {
        int    aw = *(const int*)&g_s[m0 + lr][k0 + lc];
        float4 bv = *(const float4*)&wp[(size_t)(o0 + lr) * 768 + k0 + lc];
        __syncthreads();
        As[lc + 0][lr] = (float)((aw << 24) >> 24);
        As[lc + 1][lr] = (float)((aw << 16) >> 24);
        As[lc + 2][lr] = (float)((aw << 8)  >> 24);
        As[lc + 3][lr] = (float)( aw        >> 24);
        Bs[lc + 0][lr] = bv.x; Bs[lc + 1][lr] = bv.y;
        Bs[lc + 2][lr] = bv.z; Bs[lc + 3][lr] = bv.w;
        __syncthreads();
#pragma unroll
        for (int k = 0; k < 16; k++) {
            float4 a = *(const float4*)&As[k][ty * 4];
            float4 b = *(const float4*)&Bs[k][tx * 4];
            float ar[4] = {a.x, a.y, a.z, a.w};
            float br[4] = {b.x, b.y, b.z, b.w};
#pragma unroll
            for (int i = 0; i < 4; i++)
#pragma unroll
                for (int j = 0; j < 4; j++)
                    acc[i][j] = fmaf(ar[i], br[j], acc[i][j]);
        }
    }
#pragma unroll
    for (int i = 0; i < 4; i++) {
        int m = m0 + ty * 4 + i;
#pragma unroll
        for (int j = 0; j < 4; j++) {
            int o = o0 + tx * 4 + j;
            out[(size_t)m * 768 + o] = (float)spike_of(acc[i][j]);
        }
    }
}

// ---------------------------------------------------------------------------
extern "C" void kernel_launch(void* const* d_in, const int* in_sizes, int n_in,
                              void* d_out, int out_size) {
    const float* x      = (const float*)d_in[0];
    const float* w_qkv  = (const float*)d_in[1];
    const float* w_proj = (const float*)d_in[2];
    float* out = (float*)d_out;

    cudaFuncSetAttribute(qkv_mma_kernel,
                         cudaFuncAttributeMaxDynamicSharedMemorySize, QKV_DSMEM);
    cudaFuncSetAttribute(attn_kernel,
                         cudaFuncAttributeMaxDynamicSharedMemorySize, ATTN_DSMEM);

    init_kernel<<<8, 1024>>>();
    convert_kernel<<<960, 256>>>(x, w_qkv);
    qkv_mma_kernel<<<dim3(18, 64), 256, QKV_DSMEM>>>();
    fixup_kernel<<<256, 256>>>(x, w_qkv);
    attn_kernel<<<dim3(16, 96), 128, ATTN_DSMEM>>>();
    proj_kernel<<<dim3(12, 128), 256>>>(w_proj, out);
}